// round 13
// baseline (speedup 1.0000x reference)
#include <cuda_runtime.h>

#define NP    64                 // patch size
#define CH    4                  // channels
#define PAD   192                // canvas
#define TPB   576                // 24 quad-cols x 24 rows
#define HROWS 96                 // canvas rows per block (half canvas)
#define PLW   76                 // G plane width (zero borders both sides)
#define PLH   65                 // G rows: gy in [0,64]
#define PLANE (PLW*PLH)          // 4940 floats
#define SMF   (CH*PLANE)         // 19760 floats = 79,040 B
#define ZVEC  (CH*PLH*4)         // border zero float4s: cols [0,7] & [68,75]
#define QC    24                 // quad columns (two quads: x0 and x0+96)
#define YSTEP (TPB/QC)           // 24
#define EITER (HROWS/YSTEP)      // 4 eval iterations

// out[b,y,x] = sum_c bilinear(patch_c centered, y-64-dy_c, x-64-dx_c), zero fill.
// Integer pixel coords => bilinear weights constant per (b,c):
//   out(y,x) = G_c[y+oyc+1][...], G_c = 2x2 corr(patch_c, weights), in smem.
// Each block handles a HALF canvas and builds ONLY the G rows its half needs
// (row windows of the two halves are disjoint -> no build duplication).
__global__ __launch_bounds__(TPB, 2)
void reassemble_half_kernel(const float* __restrict__ patches,
                            const float* __restrict__ pos,
                            float* __restrict__ out)
{
    extern __shared__ float sm[];        // CH planes of [PLH][PLW]
    const int b   = blockIdx.x;
    const int Y0  = blockIdx.y * HROWS;  // 0 or 96
    const int tid = threadIdx.x;

    // ---- per-channel constants ----
    int   oxc[CH], shf[CH], off0[CH], oyc[CH];
    float w00[CH], w01[CH], w10[CH], w11[CH];
    const float* pb_pos = pos + (size_t)b * 2 * CH;
    int oymin = 0x7FFFFFFF, oymax = -0x7FFFFFFF;
    #pragma unroll
    for (int c = 0; c < CH; c++) {
        const float dx = __ldg(pb_pos + c);
        const float dy = __ldg(pb_pos + CH + c);
        const float fx = -64.0f - dx;
        const float fy = -64.0f - dy;
        const float flx = floorf(fx), fly = floorf(fy);
        oxc[c] = (int)flx;
        oyc[c] = (int)fly;
        oymin = min(oymin, oyc[c]);
        oymax = max(oymax, oyc[c]);
        shf[c] = (4 - (oxc[c] & 3)) & 3;              // (oxc+shf) % 4 == 0
        off0[c] = c * PLANE + (oyc[c] + 1) * PLW + oxc[c] + shf[c] + 4;
        const float wx = fx - flx, wy = fy - fly;
        w00[c] = (1.0f - wx) * (1.0f - wy);
        w01[c] = wx * (1.0f - wy);
        w10[c] = (1.0f - wx) * wy;
        w11[c] = wx * wy;
    }

    // G rows needed by this half (union over channels), clamped to [0,64]
    const int glo = max(0, Y0 + oymin + 1);
    const int ghi = min(64, Y0 + oymax + HROWS);
    const int nrows = ghi - glo + 1;                   // may be <= 0

    // ---- zero border columns: cols [0,7] and [68,75] of every row ----
    {
        float4* smv = reinterpret_cast<float4*>(sm);
        #pragma unroll
        for (int i = tid; i < ZVEC; i += TPB) {        // 1040 vecs -> 2 iters
            const int plane = i / (PLH * 4);
            const int rem   = i - plane * (PLH * 4);
            const int row   = rem >> 2;
            const int v     = rem & 3;
            const int col4  = (v < 2) ? (v << 2) : (68 + ((v - 2) << 2));
            smv[(plane * PLANE + row * PLW + col4) >> 2] = make_float4(0.f, 0.f, 0.f, 0.f);
        }
    }
    __syncthreads();

    // ---- build only G rows [glo, ghi] (guarded taps everywhere) ----
    const float4* pin = reinterpret_cast<const float4*>(patches + (size_t)b * NP * NP * CH);
    const int npos = (nrows > 0) ? nrows * 65 : 0;
    for (int idx = tid; idx < npos; idx += TPB) {      // ~5.6 iters avg
        const int r   = idx / 65;
        const int gxi = idx - r * 65;                  // 0..64
        const int gy  = glo + r;                       // glo..ghi
        const int iy  = gy - 1;
        const int ix  = gxi - 1;

        const bool r0 = (gy >= 1), r1 = (gy <= 63);
        const bool c0 = (gxi >= 1), c1 = (gxi <= 63);
        const float4 z = make_float4(0.f, 0.f, 0.f, 0.f);
        const float4 t00 = (r0 && c0) ? __ldg(pin + iy * NP + ix)     : z;
        const float4 t01 = (r0 && c1) ? __ldg(pin + iy * NP + ix + 1) : z;
        const float4 t10 = (r1 && c0) ? __ldg(pin + gy * NP + ix)     : z;
        const float4 t11 = (r1 && c1) ? __ldg(pin + gy * NP + ix + 1) : z;

        const int rb = gy * PLW + gxi + 3;
        sm[0 * PLANE + rb + shf[0]] = t00.x * w00[0] + t01.x * w01[0] + t10.x * w10[0] + t11.x * w11[0];
        sm[1 * PLANE + rb + shf[1]] = t00.y * w00[1] + t01.y * w01[1] + t10.y * w10[1] + t11.y * w11[1];
        sm[2 * PLANE + rb + shf[2]] = t00.z * w00[2] + t01.z * w01[2] + t10.z * w10[2] + t11.z * w11[2];
        sm[3 * PLANE + rb + shf[3]] = t00.w * w00[3] + t01.w * w01[3] + t10.w * w10[3] + t11.w * w11[3];
    }
    __syncthreads();

    // ---- eval: two quads per thread (x0 and x0+96), same y ----
    const int qcol = tid % QC;                          // 0..23
    const int x0   = qcol * 4;                          // 0..92
    int y = Y0 + tid / QC;                              // Y0..Y0+23

    int  ylo[CH], fb[CH];
    bool xaok[CH], xbok[CH];
    #pragma unroll
    for (int c = 0; c < CH; c++) {
        ylo[c]  = -1 - oyc[c];                          // iy = y+oy in [-1,63]
        xaok[c] = ((unsigned)(x0      + oxc[c] + 4) <= 71u);
        xbok[c] = ((unsigned)(x0 + 96 + oxc[c] + 4) <= 71u);
        fb[c]   = off0[c] + x0;
    }

    float* po = out + (size_t)b * PAD * PAD + (size_t)y * PAD + x0;
    int ywf = y * PLW;

    #pragma unroll
    for (int q = 0; q < EITER; q++) {
        float a0 = 0.f, a1 = 0.f, a2 = 0.f, a3 = 0.f;
        float b0 = 0.f, b1 = 0.f, b2 = 0.f, b3 = 0.f;

        #pragma unroll
        for (int c = 0; c < CH; c++) {
            // near-warp-uniform branch: skip channel when y outside window
            if ((unsigned)(y - ylo[c]) <= 64u) {
                const float* p = sm + fb[c] + ywf;
                if (xaok[c]) {
                    const float4 g = *reinterpret_cast<const float4*>(p);
                    a0 += g.x; a1 += g.y; a2 += g.z; a3 += g.w;
                }
                if (xbok[c]) {
                    const float4 g = *reinterpret_cast<const float4*>(p + 96);
                    b0 += g.x; b1 += g.y; b2 += g.z; b3 += g.w;
                }
            }
        }

        float4 oA; oA.x = a0; oA.y = a1; oA.z = a2; oA.w = a3;
        float4 oB; oB.x = b0; oB.y = b1; oB.z = b2; oB.w = b3;
        *reinterpret_cast<float4*>(po)      = oA;
        *reinterpret_cast<float4*>(po + 96) = oB;

        y   += YSTEP;
        ywf += YSTEP * PLW;
        po  += YSTEP * PAD;
    }
}

extern "C" void kernel_launch(void* const* d_in, const int* in_sizes, int n_in,
                              void* d_out, int out_size) {
    const float* patches = (const float*)d_in[0];   // (B, 64, 64, 4) fp32
    const float* pos     = (const float*)d_in[1];   // (B, 1, 2, 4)  fp32
    float* out           = (float*)d_out;           // (B, 192, 192, 1) fp32

    const int B = out_size / (PAD * PAD);           // 512
    const int smem_bytes = SMF * sizeof(float);     // 79,040 B
    static bool attr_set = false;
    if (!attr_set) {
        cudaFuncSetAttribute(reassemble_half_kernel,
                             cudaFuncAttributeMaxDynamicSharedMemorySize, smem_bytes);
        attr_set = true;
    }
    dim3 grid(B, 2);                                // half-canvas blocks
    reassemble_half_kernel<<<grid, TPB, smem_bytes>>>(patches, pos, out);
}

// round 15
// speedup vs baseline: 1.2182x; 1.2182x over previous
#include <cuda_runtime.h>

#define NP    64                 // patch size
#define CH    4                  // channels
#define PAD   192                // canvas
#define TPB   768                // 24 quad-cols x 32 rows
#define PLW   76                 // G plane width (zero borders both sides)
#define PLH   65                 // G rows: gy in [0,64]
#define PLANE (PLW*PLH)          // 4940 floats
#define SMF   (CH*PLANE)         // 19760 floats = 79,040 B (2 blocks/SM)
#define GIN   (63*63)            // interior G positions per channel
#define GBRD  256                // border G positions per channel
#define ZVEC  (CH*PLH*4)         // border zero float4s: cols [0,7] & [68,75]
#define QC    24                 // quad columns; two quads at x0 and x0+96
#define YSTEP (TPB/QC)           // 32
#define EITER (PAD/YSTEP)        // 6 eval iterations

// out[b,y,x] = sum_c bilinear(patch_c centered, y-64-dy_c, x-64-dx_c), zero fill.
// Integer pixel coords => bilinear weights constant per (b,c):
//   out(y,x) = G_c[y+oyc+1][...], G_c = 2x2 corr(patch_c, weights), in smem.
// TPB=768 with 2 blocks/SM -> 48 warps/SM (occupancy push); eval is the
// proven two-quads-spaced-96 pattern with a near-uniform y-window branch.
__global__ __launch_bounds__(TPB, 2)
void reassemble_w48_kernel(const float* __restrict__ patches,
                           const float* __restrict__ pos,
                           float* __restrict__ out)
{
    extern __shared__ float sm[];        // CH planes of [PLH][PLW]
    const int b   = blockIdx.x;
    const int tid = threadIdx.x;

    // ---- per-channel constants ----
    int   oxc[CH], shf[CH], off0[CH], oyc[CH];
    float w00[CH], w01[CH], w10[CH], w11[CH];
    const float* pb_pos = pos + (size_t)b * 2 * CH;
    #pragma unroll
    for (int c = 0; c < CH; c++) {
        const float dx = __ldg(pb_pos + c);
        const float dy = __ldg(pb_pos + CH + c);
        const float fx = -64.0f - dx;
        const float fy = -64.0f - dy;
        const float flx = floorf(fx), fly = floorf(fy);
        oxc[c] = (int)flx;
        oyc[c] = (int)fly;
        shf[c] = (4 - (oxc[c] & 3)) & 3;              // (oxc+shf) % 4 == 0
        off0[c] = c * PLANE + (oyc[c] + 1) * PLW + oxc[c] + shf[c] + 4;
        const float wx = fx - flx, wy = fy - fly;
        w00[c] = (1.0f - wx) * (1.0f - wy);
        w01[c] = wx * (1.0f - wy);
        w10[c] = (1.0f - wx) * wy;
        w11[c] = wx * wy;
    }

    // ---- zero border columns: cols [0,7] and [68,75] of every row ----
    {
        float4* smv = reinterpret_cast<float4*>(sm);
        #pragma unroll
        for (int i = tid; i < ZVEC; i += TPB) {        // 1040 vecs -> ~2 iters
            const int plane = i / (PLH * 4);
            const int rem   = i - plane * (PLH * 4);
            const int row   = rem >> 2;
            const int v     = rem & 3;
            const int col4  = (v < 2) ? (v << 2) : (68 + ((v - 2) << 2));
            smv[(plane * PLANE + row * PLW + col4) >> 2] = make_float4(0.f, 0.f, 0.f, 0.f);
        }
    }
    __syncthreads();

    // ---- build G planes: interior (no tap guards) ----
    const float4* pin = reinterpret_cast<const float4*>(patches + (size_t)b * NP * NP * CH);
    for (int idx = tid; idx < GIN; idx += TPB) {       // ~5.2 iters
        const int r   = idx / 63;                      // 0..62
        const int gxi = idx - r * 63 + 1;              // 1..63
        const int gy  = r + 1;                         // 1..63
        const int ix  = gxi - 1;

        const float4 t00 = __ldg(pin + (gy - 1) * NP + ix);
        const float4 t01 = __ldg(pin + (gy - 1) * NP + ix + 1);
        const float4 t10 = __ldg(pin + gy * NP + ix);
        const float4 t11 = __ldg(pin + gy * NP + ix + 1);

        const int rb = gy * PLW + gxi + 3;
        sm[0 * PLANE + rb + shf[0]] = t00.x * w00[0] + t01.x * w01[0] + t10.x * w10[0] + t11.x * w11[0];
        sm[1 * PLANE + rb + shf[1]] = t00.y * w00[1] + t01.y * w01[1] + t10.y * w10[1] + t11.y * w11[1];
        sm[2 * PLANE + rb + shf[2]] = t00.z * w00[2] + t01.z * w01[2] + t10.z * w10[2] + t11.z * w11[2];
        sm[3 * PLANE + rb + shf[3]] = t00.w * w00[3] + t01.w * w01[3] + t10.w * w10[3] + t11.w * w11[3];
    }

    // ---- build G planes: 256 border positions (guarded taps) ----
    if (tid < GBRD) {
        int gy, gxi;
        if (tid < 65)       { gy = 0;         gxi = tid; }
        else if (tid < 130) { gy = 64;        gxi = tid - 65; }
        else if (tid < 193) { gy = tid - 129; gxi = 0;  }   // 1..63
        else                { gy = tid - 192; gxi = 64; }   // 1..63
        const int iy = gy - 1;
        const int ix = gxi - 1;
        const bool r0 = (gy >= 1), r1 = (gy <= 63);
        const bool c0 = (gxi >= 1), c1 = (gxi <= 63);
        const float4 z = make_float4(0.f, 0.f, 0.f, 0.f);
        const float4 t00 = (r0 && c0) ? __ldg(pin + iy * NP + ix)     : z;
        const float4 t01 = (r0 && c1) ? __ldg(pin + iy * NP + ix + 1) : z;
        const float4 t10 = (r1 && c0) ? __ldg(pin + gy * NP + ix)     : z;
        const float4 t11 = (r1 && c1) ? __ldg(pin + gy * NP + ix + 1) : z;

        const int rb = gy * PLW + gxi + 3;
        sm[0 * PLANE + rb + shf[0]] = t00.x * w00[0] + t01.x * w01[0] + t10.x * w10[0] + t11.x * w11[0];
        sm[1 * PLANE + rb + shf[1]] = t00.y * w00[1] + t01.y * w01[1] + t10.y * w10[1] + t11.y * w11[1];
        sm[2 * PLANE + rb + shf[2]] = t00.z * w00[2] + t01.z * w01[2] + t10.z * w10[2] + t11.z * w11[2];
        sm[3 * PLANE + rb + shf[3]] = t00.w * w00[3] + t01.w * w01[3] + t10.w * w10[3] + t11.w * w11[3];
    }
    __syncthreads();

    // ---- eval: two quads per thread (x0 and x0+96), same y ----
    const int qcol = tid % QC;                          // 0..23
    const int x0   = qcol * 4;                          // 0..92
    int y = tid / QC;                                   // 0..31

    int  ylo[CH], fb[CH];
    bool xaok[CH], xbok[CH];
    #pragma unroll
    for (int c = 0; c < CH; c++) {
        ylo[c]  = -1 - oyc[c];                          // iy = y+oy in [-1,63]
        xaok[c] = ((unsigned)(x0      + oxc[c] + 4) <= 71u);
        xbok[c] = ((unsigned)(x0 + 96 + oxc[c] + 4) <= 71u);
        fb[c]   = off0[c] + x0;
    }

    float* po = out + (size_t)b * PAD * PAD + (size_t)y * PAD + x0;
    int ywf = y * PLW;

    #pragma unroll
    for (int q = 0; q < EITER; q++) {
        float a0 = 0.f, a1 = 0.f, a2 = 0.f, a3 = 0.f;
        float b0 = 0.f, b1 = 0.f, b2 = 0.f, b3 = 0.f;

        #pragma unroll
        for (int c = 0; c < CH; c++) {
            // near-warp-uniform branch: skip channel when y outside window
            if ((unsigned)(y - ylo[c]) <= 64u) {
                const float* p = sm + fb[c] + ywf;
                if (xaok[c]) {
                    const float4 g = *reinterpret_cast<const float4*>(p);
                    a0 += g.x; a1 += g.y; a2 += g.z; a3 += g.w;
                }
                if (xbok[c]) {
                    const float4 g = *reinterpret_cast<const float4*>(p + 96);
                    b0 += g.x; b1 += g.y; b2 += g.z; b3 += g.w;
                }
            }
        }

        float4 oA; oA.x = a0; oA.y = a1; oA.z = a2; oA.w = a3;
        float4 oB; oB.x = b0; oB.y = b1; oB.z = b2; oB.w = b3;
        *reinterpret_cast<float4*>(po)      = oA;
        *reinterpret_cast<float4*>(po + 96) = oB;

        y   += YSTEP;
        ywf += YSTEP * PLW;
        po  += YSTEP * PAD;
    }
}

extern "C" void kernel_launch(void* const* d_in, const int* in_sizes, int n_in,
                              void* d_out, int out_size) {
    const float* patches = (const float*)d_in[0];   // (B, 64, 64, 4) fp32
    const float* pos     = (const float*)d_in[1];   // (B, 1, 2, 4)  fp32
    float* out           = (float*)d_out;           // (B, 192, 192, 1) fp32

    const int B = out_size / (PAD * PAD);           // 512
    const int smem_bytes = SMF * sizeof(float);     // 79,040 B
    static bool attr_set = false;
    if (!attr_set) {
        cudaFuncSetAttribute(reassemble_w48_kernel,
                             cudaFuncAttributeMaxDynamicSharedMemorySize, smem_bytes);
        attr_set = true;
    }
    reassemble_w48_kernel<<<B, TPB, smem_bytes>>>(patches, pos, out);
}